// round 1
// baseline (speedup 1.0000x reference)
#include <cuda_runtime.h>

#define BATCH 64
#define NCAP  16
#define DCAP  64
#define NIN   512
#define DIN   1024
#define NOUT  (NCAP*DCAP)   // 1024

// ---------------- scratch (allocation-free: __device__ globals) ----------------
__device__ float g_uhat[(size_t)BATCH * NCAP * NIN * DCAP];  // 128 MB, layout [b][cap][j][d]
__device__ float g_b0[BATCH * NCAP * NIN];                    // routing logits ping
__device__ float g_b1[BATCH * NCAP * NIN];                    // routing logits pong

// ---------------- helpers ----------------
__device__ __forceinline__ unsigned f2tf(float x) {
    unsigned r;
    asm("cvt.rna.tf32.f32 %0, %1;" : "=r"(r) : "f"(x));
    return r;
}

__device__ __forceinline__ void mma8(float* d, const unsigned* a, const unsigned* b) {
    asm volatile(
        "mma.sync.aligned.m16n8k8.row.col.f32.tf32.tf32.f32 "
        "{%0,%1,%2,%3}, {%4,%5,%6,%7}, {%8,%9}, {%0,%1,%2,%3};\n"
        : "+f"(d[0]), "+f"(d[1]), "+f"(d[2]), "+f"(d[3])
        : "r"(a[0]), "r"(a[1]), "r"(a[2]), "r"(a[3]),
          "r"(b[0]), "r"(b[1]));
}

// ---------------- GEMM: u_hat = x @ W, fused transpose into [b][cap][j][d] ----------------
// M = BATCH*NIN = 32768, N = 1024, K = 1024. CTA tile 128x128x16, 8 warps (2x4), warp tile 64x32.
#define BM 128
#define BN 128
#define BK 16
#define PA 20    // A smem row pitch (floats): conflict-free for frag loads
#define PB 136   // B smem row pitch (floats): conflict-free for frag loads

__global__ __launch_bounds__(256) void gemm_kernel(const float* __restrict__ X,
                                                   const float* __restrict__ Wm) {
    __shared__ float As[2][BM * PA];
    __shared__ float Bs[2][BK * PB];

    const int tid  = threadIdx.x;
    const int lane = tid & 31;
    const int warp = tid >> 5;
    const int wm   = warp >> 2;   // 0..1
    const int wn   = warp & 3;    // 0..3
    const int m0   = blockIdx.y * BM;
    const int n0   = blockIdx.x * BN;

    float acc[4][4][4];
#pragma unroll
    for (int a = 0; a < 4; a++)
#pragma unroll
        for (int b = 0; b < 4; b++)
#pragma unroll
            for (int c = 0; c < 4; c++) acc[a][b][c] = 0.f;

    float4 areg[2], breg[2];

    // per-thread static load coords
    const int v0  = tid;
    const int v1  = tid + 256;
    const int arA0 = v0 >> 2,  acA0 = (v0 & 3) << 2;
    const int arA1 = v1 >> 2,  acA1 = (v1 & 3) << 2;
    const int brB0 = v0 >> 5,  bcB0 = (v0 & 31) << 2;
    const int brB1 = v1 >> 5,  bcB1 = (v1 & 31) << 2;

#define LDG_TILE(kt)                                                                     \
    do {                                                                                 \
        areg[0] = *(const float4*)&X[(size_t)(m0 + arA0) * DIN + (kt) * BK + acA0];      \
        areg[1] = *(const float4*)&X[(size_t)(m0 + arA1) * DIN + (kt) * BK + acA1];      \
        breg[0] = *(const float4*)&Wm[(size_t)((kt) * BK + brB0) * NOUT + n0 + bcB0];    \
        breg[1] = *(const float4*)&Wm[(size_t)((kt) * BK + brB1) * NOUT + n0 + bcB1];    \
    } while (0)

#define STS_TILE(buf)                                                                    \
    do {                                                                                 \
        float* pa0 = &As[buf][arA0 * PA + acA0];                                         \
        pa0[0] = __uint_as_float(f2tf(areg[0].x));                                       \
        pa0[1] = __uint_as_float(f2tf(areg[0].y));                                       \
        pa0[2] = __uint_as_float(f2tf(areg[0].z));                                       \
        pa0[3] = __uint_as_float(f2tf(areg[0].w));                                       \
        float* pa1 = &As[buf][arA1 * PA + acA1];                                         \
        pa1[0] = __uint_as_float(f2tf(areg[1].x));                                       \
        pa1[1] = __uint_as_float(f2tf(areg[1].y));                                       \
        pa1[2] = __uint_as_float(f2tf(areg[1].z));                                       \
        pa1[3] = __uint_as_float(f2tf(areg[1].w));                                       \
        float* pb0 = &Bs[buf][brB0 * PB + bcB0];                                         \
        pb0[0] = __uint_as_float(f2tf(breg[0].x));                                       \
        pb0[1] = __uint_as_float(f2tf(breg[0].y));                                       \
        pb0[2] = __uint_as_float(f2tf(breg[0].z));                                       \
        pb0[3] = __uint_as_float(f2tf(breg[0].w));                                       \
        float* pb1 = &Bs[buf][brB1 * PB + bcB1];                                         \
        pb1[0] = __uint_as_float(f2tf(breg[1].x));                                       \
        pb1[1] = __uint_as_float(f2tf(breg[1].y));                                       \
        pb1[2] = __uint_as_float(f2tf(breg[1].z));                                       \
        pb1[3] = __uint_as_float(f2tf(breg[1].w));                                       \
    } while (0)

    LDG_TILE(0);
    STS_TILE(0);
    __syncthreads();

    const int NKT = DIN / BK;  // 64
    for (int kt = 0; kt < NKT; kt++) {
        const int buf = kt & 1;
        if (kt + 1 < NKT) LDG_TILE(kt + 1);

#pragma unroll
        for (int ks = 0; ks < 2; ks++) {
            const int kk = ks * 8;
            unsigned af[4][4], bf[4][2];
#pragma unroll
            for (int mf = 0; mf < 4; mf++) {
                const int r  = wm * 64 + mf * 16 + (lane >> 2);
                const int cb = kk + (lane & 3);
                af[mf][0] = __float_as_uint(As[buf][r * PA + cb]);
                af[mf][1] = __float_as_uint(As[buf][(r + 8) * PA + cb]);
                af[mf][2] = __float_as_uint(As[buf][r * PA + cb + 4]);
                af[mf][3] = __float_as_uint(As[buf][(r + 8) * PA + cb + 4]);
            }
#pragma unroll
            for (int nf = 0; nf < 4; nf++) {
                const int col = wn * 32 + nf * 8 + (lane >> 2);
                const int rr  = kk + (lane & 3);
                bf[nf][0] = __float_as_uint(Bs[buf][rr * PB + col]);
                bf[nf][1] = __float_as_uint(Bs[buf][(rr + 4) * PB + col]);
            }
#pragma unroll
            for (int mf = 0; mf < 4; mf++)
#pragma unroll
                for (int nf = 0; nf < 4; nf++) mma8(acc[mf][nf], af[mf], bf[nf]);
        }
        __syncthreads();
        if (kt + 1 < NKT) {
            STS_TILE(1 - buf);
            __syncthreads();
        }
    }

    // epilogue: write u_hat in [b][cap][j][d] layout directly
#pragma unroll
    for (int mf = 0; mf < 4; mf++) {
#pragma unroll
        for (int nf = 0; nf < 4; nf++) {
            const int row = m0 + wm * 64 + mf * 16 + (lane >> 2);
            const int col = n0 + wn * 32 + nf * 8 + ((lane & 3) << 1);
            const int bb = row >> 9;          // batch
            const int j  = row & 511;         // n_in index
            const int ii = col >> 6;          // capsule
            const int d  = col & 63;          // dim index (even)
            size_t base = ((((size_t)bb * NCAP + ii) * NIN) + j) * DCAP + d;
            *(float2*)&g_uhat[base] = make_float2(acc[mf][nf][0], acc[mf][nf][1]);
            // row+8 stays inside the same 512-row batch block (tile is 128-aligned)
            size_t base2 = base + (size_t)8 * DCAP;
            *(float2*)&g_uhat[base2] = make_float2(acc[mf][nf][2], acc[mf][nf][3]);
        }
    }
#undef LDG_TILE
#undef STS_TILE
}

// ---------------- routing: one CTA per (b, capsule); u_hat slice cached in SMEM ----------------
#define PU 65  // padded row pitch for the 512x64 slice (conflict-free both access patterns)
#define ROUTE_SMEM ((NIN * PU + NIN + 256 + 64 + 8) * 4)

__global__ __launch_bounds__(256) void route_kernel(float* __restrict__ d_out,
                                                    int first, int last, int ping) {
    extern __shared__ float sm[];
    float* U    = sm;                  // 512 * 65
    float* c    = U + NIN * PU;        // 512
    float* part = c + NIN;             // 256
    float* outv = part + 256;          // 64
    float* red  = outv + 64;           // 2

    const int i   = blockIdx.x;   // capsule
    const int b   = blockIdx.y;   // batch
    const int tid = threadIdx.x;

    // stage this (b,i) u_hat slice into SMEM: 512x64 f32 = 128 KB
    const float4* src4 = (const float4*)(g_uhat + ((size_t)(b * NCAP + i)) * (NIN * DCAP));
    for (int v = tid; v < NIN * 16; v += 256) {
        float4 t   = src4[v];
        int    j   = v >> 4;
        int    cv  = (v & 15) << 2;
        float* dst = U + j * PU + cv;
        dst[0] = t.x; dst[1] = t.y; dst[2] = t.z; dst[3] = t.w;
    }

    const float* b_in = ping ? g_b1 : g_b0;

    // coupling coefficients: softmax over the 16 capsules per (b, j)
    if (first) {
        for (int j = tid; j < NIN; j += 256) c[j] = 0.0625f;
    } else {
        for (int j = tid; j < NIN; j += 256) {
            const float* bp = b_in + ((size_t)b * NCAP) * NIN + j;
            float vals[NCAP];
            float m = -1e30f;
#pragma unroll
            for (int q = 0; q < NCAP; q++) {
                vals[q] = bp[q * NIN];
                m       = fmaxf(m, vals[q]);
            }
            float s = 0.f;
#pragma unroll
            for (int q = 0; q < NCAP; q++) s += expf(vals[q] - m);
            c[j] = expf(vals[i] - m) / s;
        }
    }
    __syncthreads();

    // out[d] = sum_j c[j] * U[j][d]  (4-way split reduction over j)
    {
        const int d = tid & 63, g = tid >> 6;
        float acc = 0.f;
        for (int j = g; j < NIN; j += 4) acc = fmaf(c[j], U[j * PU + d], acc);
        part[(g << 6) + d] = acc;
    }
    __syncthreads();
    if (tid < 64) outv[tid] = part[tid] + part[64 + tid] + part[128 + tid] + part[192 + tid];
    __syncthreads();

    // squash: v / sqrt(||v||^2 + 1e-7)
    if (tid < 64) {
        float o  = outv[tid];
        float sq = o * o;
#pragma unroll
        for (int off = 16; off; off >>= 1) sq += __shfl_xor_sync(0xffffffffu, sq, off);
        if ((tid & 31) == 0) red[tid >> 5] = sq;
    }
    __syncthreads();
    const float inv = 1.0f / sqrtf(red[0] + red[1] + 1e-7f);
    if (tid < 64) outv[tid] *= inv;
    __syncthreads();

    if (last) {
        if (tid < 64) d_out[((size_t)(b * NCAP + i)) * DCAP + tid] = outv[tid];
    } else {
        float* b_out = ping ? g_b0 : g_b1;
        for (int j = tid; j < NIN; j += 256) {
            float dot = 0.f;
#pragma unroll
            for (int d2 = 0; d2 < DCAP; d2++) dot = fmaf(outv[d2], U[j * PU + d2], dot);
            b_out[((size_t)(b * NCAP + i)) * NIN + j] = dot;
        }
    }
}

// ---------------- launch ----------------
extern "C" void kernel_launch(void* const* d_in, const int* in_sizes, int n_in,
                              void* d_out, int out_size) {
    const float* x = (const float*)d_in[0];
    const float* W = (const float*)d_in[1];
    // defensive: if metadata ordered W first, swap by size
    if (in_sizes[0] == DIN * NOUT && in_sizes[1] == (int)((size_t)BATCH * NIN * DIN)) {
        const float* t = x; x = W; W = t;
    }
    float* out = (float*)d_out;

    cudaFuncSetAttribute(route_kernel, cudaFuncAttributeMaxDynamicSharedMemorySize, ROUTE_SMEM);

    gemm_kernel<<<dim3(NOUT / BN, (BATCH * NIN) / BM), 256>>>(x, W);

    // iter 0: uniform c, write logits -> g_b0 (ping=1 => b_out = g_b0)
    route_kernel<<<dim3(NCAP, BATCH), 256, ROUTE_SMEM>>>(out, 1, 0, 1);
    // iter 1: read g_b0, write g_b1
    route_kernel<<<dim3(NCAP, BATCH), 256, ROUTE_SMEM>>>(out, 0, 0, 0);
    // iter 2 (last): read g_b1, write final outputs
    route_kernel<<<dim3(NCAP, BATCH), 256, ROUTE_SMEM>>>(out, 0, 1, 1);
}

// round 5
// speedup vs baseline: 1.6869x; 1.6869x over previous
#include <cuda_runtime.h>
#include <cuda_fp16.h>
#include <cstdint>

#define BATCH 64
#define NCAP  16
#define DCAP  64
#define NIN   512
#define DIN   1024
#define NOUT  1024

// ---------------- scratch (allocation-free: __device__ globals) ----------------
__device__ float  g_uhat[(size_t)BATCH * NCAP * NIN * DCAP];  // 128 MB, [b][cap][j][d]
__device__ __half g_xh[(size_t)BATCH * NIN * DIN];            // 64 MB, x in f16 (rn)
__device__ __half g_wh[(size_t)NOUT * DIN];                   // 2 MB, W^T [n][k] f16 (rn)
__device__ float  g_b0[BATCH * NCAP * NIN];                   // fallback routing logits
__device__ float  g_b1[BATCH * NCAP * NIN];

// ---------------- helpers ----------------
__device__ __forceinline__ uint32_t smem_u32(const void* p) {
    uint32_t a;
    asm("{ .reg .u64 t; cvta.to.shared.u64 t, %1; cvt.u32.u64 %0, t; }" : "=r"(a) : "l"(p));
    return a;
}
__device__ __forceinline__ void cp16(uint32_t dst, const void* src) {
    asm volatile("cp.async.cg.shared.global [%0], [%1], 16;\n" :: "r"(dst), "l"(src));
}
__device__ __forceinline__ void cp_commit() { asm volatile("cp.async.commit_group;\n" ::: "memory"); }

__device__ __forceinline__ void hmma(float* d, const uint32_t* a, const uint32_t* b) {
    asm volatile(
        "mma.sync.aligned.m16n8k16.row.col.f32.f16.f16.f32 "
        "{%0,%1,%2,%3}, {%4,%5,%6,%7}, {%8,%9}, {%0,%1,%2,%3};\n"
        : "+f"(d[0]), "+f"(d[1]), "+f"(d[2]), "+f"(d[3])
        : "r"(a[0]), "r"(a[1]), "r"(a[2]), "r"(a[3]), "r"(b[0]), "r"(b[1]));
}

#define CLUSTER_SYNC() do {                                              \
    asm volatile("barrier.cluster.arrive.aligned;" ::: "memory");        \
    asm volatile("barrier.cluster.wait.aligned;" ::: "memory");          \
} while (0)

// ---------------- prep: x f32 -> f16 rn ----------------
__global__ __launch_bounds__(256) void xh_kernel(const float* __restrict__ X) {
    const size_t n4 = (size_t)BATCH * NIN * DIN / 4;
    for (size_t i = (size_t)blockIdx.x * blockDim.x + threadIdx.x; i < n4;
         i += (size_t)gridDim.x * blockDim.x) {
        float4 v = ((const float4*)X)[i];
        __half2* dst = (__half2*)g_xh + i * 2;
        dst[0] = __floats2half2_rn(v.x, v.y);
        dst[1] = __floats2half2_rn(v.z, v.w);
    }
}

// ---------------- prep: W [k][n] f32 -> W^T [n][k] f16 rn ----------------
__global__ __launch_bounds__(256) void wh_kernel(const float* __restrict__ W) {
    __shared__ float t[32][33];
    const int n0 = blockIdx.x * 32, k0 = blockIdx.y * 32;
    const int tx = threadIdx.x, ty = threadIdx.y;  // 32 x 8
#pragma unroll
    for (int r = 0; r < 32; r += 8)
        t[ty + r][tx] = W[(size_t)(k0 + ty + r) * NOUT + n0 + tx];
    __syncthreads();
#pragma unroll
    for (int r = 0; r < 32; r += 8)
        g_wh[(size_t)(n0 + ty + r) * DIN + k0 + tx] = __float2half_rn(t[tx][ty + r]);
}

// ---------------- GEMM: fp16 mma.sync m16n8k16, CTA 128x256x32, 4-stage cp.async ----------------
#define GM 128
#define GN 256
#define GK 32
#define PIT 80                      // bytes per SMEM row (40 halves) — conflict-free pitch
#define A_SZ (GM * PIT)             // 10240
#define B_SZ (GN * PIT)             // 20480
#define ST_SZ (A_SZ + B_SZ)         // 30720
#define NSTG 4
#define GEMM_SMEM (NSTG * ST_SZ)    // 122880
#define NKT (DIN / GK)              // 32

__global__ __launch_bounds__(512, 1) void gemm_f16() {
    extern __shared__ char smc[];
    const uint32_t sb = smem_u32(smc);
    const int tid  = threadIdx.x;
    const int lane = tid & 31;
    const int warp = tid >> 5;       // 16 warps
    const int wm   = warp >> 3;      // 0..1  (64 rows each)
    const int wn   = warp & 7;       // 0..7  (32 cols each)
    const int m0   = blockIdx.y * GM;
    const int n0   = blockIdx.x * GN;

    float acc[4][4][4];
#pragma unroll
    for (int a = 0; a < 4; a++)
#pragma unroll
        for (int b = 0; b < 4; b++)
#pragma unroll
            for (int c = 0; c < 4; c++) acc[a][b][c] = 0.f;

    const int ra = tid >> 2, ca = tid & 3;   // A chunk coords (512 chunks)
    auto load_stage = [&](int kt) {
        const uint32_t base = sb + (uint32_t)(kt & 3) * ST_SZ;
        const int kb = kt * GK;
        // A: 128 rows x 4 chunks
        cp16(base + ra * PIT + ca * 16, g_xh + (size_t)(m0 + ra) * DIN + kb + ca * 8);
        // B: 256 rows x 4 chunks (two waves)
        cp16(base + A_SZ + ra * PIT + ca * 16, g_wh + (size_t)(n0 + ra) * DIN + kb + ca * 8);
        cp16(base + A_SZ + (128 + ra) * PIT + ca * 16,
             g_wh + (size_t)(n0 + 128 + ra) * DIN + kb + ca * 8);
        cp_commit();
    };

    load_stage(0);
    load_stage(1);
    load_stage(2);

    for (int kt = 0; kt < NKT; kt++) {
        if (kt < NKT - 2)      asm volatile("cp.async.wait_group 2;\n" ::: "memory");
        else if (kt == NKT - 2) asm volatile("cp.async.wait_group 1;\n" ::: "memory");
        else                    asm volatile("cp.async.wait_group 0;\n" ::: "memory");
        __syncthreads();

        const char* ab = smc + (kt & 3) * ST_SZ;
        const char* bb = ab + A_SZ;
        const int cb = (lane & 3) * 4;   // byte offset of this lane's k-pair (2 halves)

#pragma unroll
        for (int ks = 0; ks < 2; ks++) {
            const int kkb = ks * 32;     // byte offset of k-step (16 halves)
            uint32_t af[4][4], bf[4][2];
#pragma unroll
            for (int mf = 0; mf < 4; mf++) {
                const int r = wm * 64 + mf * 16 + (lane >> 2);
                af[mf][0] = *(const uint32_t*)(ab + r * PIT + kkb + cb);
                af[mf][1] = *(const uint32_t*)(ab + (r + 8) * PIT + kkb + cb);
                af[mf][2] = *(const uint32_t*)(ab + r * PIT + kkb + cb + 16);
                af[mf][3] = *(const uint32_t*)(ab + (r + 8) * PIT + kkb + cb + 16);
            }
#pragma unroll
            for (int nf = 0; nf < 4; nf++) {
                const int n = wn * 32 + nf * 8 + (lane >> 2);
                bf[nf][0] = *(const uint32_t*)(bb + n * PIT + kkb + cb);
                bf[nf][1] = *(const uint32_t*)(bb + n * PIT + kkb + cb + 16);
            }
#pragma unroll
            for (int mf = 0; mf < 4; mf++)
#pragma unroll
                for (int nf = 0; nf < 4; nf++) hmma(acc[mf][nf], af[mf], bf[nf]);
        }

        if (kt + 3 < NKT) load_stage(kt + 3);
    }

    // epilogue: write u_hat in [b][cap][j][d] layout
#pragma unroll
    for (int mf = 0; mf < 4; mf++) {
#pragma unroll
        for (int nf = 0; nf < 4; nf++) {
            const int row = m0 + wm * 64 + mf * 16 + (lane >> 2);
            const int col = n0 + wn * 32 + nf * 8 + ((lane & 3) << 1);
            const int bb2 = row >> 9;
            const int j   = row & (NIN - 1);
            const int cap = col >> 6;
            const int d   = col & 63;
            size_t base = (((size_t)(bb2 * NCAP + cap) * NIN) + j) * DCAP + d;
            *(float2*)&g_uhat[base] = make_float2(acc[mf][nf][0], acc[mf][nf][1]);
            *(float2*)&g_uhat[base + (size_t)8 * DCAP] = make_float2(acc[mf][nf][2], acc[mf][nf][3]);
        }
    }
}

// ---------------- fused routing: cluster of 16 CTAs (one per capsule) per batch ----------------
#define PU 65
#define RF_SMEM ((NIN * PU + NIN + NIN + 512 + 64 + 8) * 4)

__global__ __launch_bounds__(512, 1) void route_fused(float* __restrict__ d_out) {
    extern __shared__ float sm[];
    float* U     = sm;                 // 512 * 65
    float* mylog = U + NIN * PU;       // 512 (this capsule's logits, DSMEM-visible)
    float* carr  = mylog + NIN;        // 512 coupling coeffs
    float* part  = carr + 512;         // 512 (8 groups x 64)
    float* outv  = part + 512;         // 64
    float* red   = outv + 64;          // 2

    const int i   = blockIdx.x;   // capsule == cluster rank
    const int b   = blockIdx.y;   // batch
    const int tid = threadIdx.x;

    // stage u_hat slice (512x64 f32 = 128KB) once
    const float4* src4 = (const float4*)(g_uhat + ((size_t)(b * NCAP + i)) * (NIN * DCAP));
#pragma unroll 4
    for (int v = tid; v < NIN * 16; v += 512) {
        float4 t   = src4[v];
        float* dst = U + (v >> 4) * PU + ((v & 15) << 2);
        dst[0] = t.x; dst[1] = t.y; dst[2] = t.z; dst[3] = t.w;
    }
    __syncthreads();

    const uint32_t laddr = smem_u32(&mylog[tid]);

    for (int it = 0; it < 3; it++) {
        float cj;
        if (it == 0) {
            cj = 0.0625f;
        } else {
            // softmax over the 16 capsules: read every rank's logit for my j=tid
            float vals[NCAP];
#pragma unroll
            for (int r = 0; r < NCAP; r++) {
                uint32_t ra;
                asm("mapa.shared::cluster.u32 %0, %1, %2;" : "=r"(ra) : "r"(laddr), "r"(r));
                asm volatile("ld.shared::cluster.f32 %0, [%1];" : "=f"(vals[r]) : "r"(ra));
            }
            float m = -1e30f;
#pragma unroll
            for (int q = 0; q < NCAP; q++) m = fmaxf(m, vals[q]);
            float s = 0.f;
#pragma unroll
            for (int q = 0; q < NCAP; q++) s += expf(vals[q] - m);
            cj = expf(vals[i] - m) / s;
            CLUSTER_SYNC();  // all reads done before anyone overwrites mylog
        }
        carr[tid] = cj;
        __syncthreads();

        // out[d] = sum_j c[j] * U[j][d]
        {
            const int d = tid & 63, g = tid >> 6;
            float a = 0.f;
#pragma unroll 4
            for (int j = g; j < NIN; j += 8) a = fmaf(carr[j], U[j * PU + d], a);
            part[(g << 6) + d] = a;
        }
        __syncthreads();
        if (tid < 64) {
            float s = 0.f;
#pragma unroll
            for (int q = 0; q < 8; q++) s += part[(q << 6) + tid];
            outv[tid] = s;
        }
        __syncthreads();
        if (tid < 64) {
            float o  = outv[tid];
            float sq = o * o;
#pragma unroll
            for (int off = 16; off; off >>= 1) sq += __shfl_xor_sync(0xffffffffu, sq, off);
            if ((tid & 31) == 0) red[tid >> 5] = sq;
        }
        __syncthreads();
        const float inv = 1.0f / sqrtf(red[0] + red[1] + 1e-7f);
        if (tid < 64) outv[tid] *= inv;
        __syncthreads();

        if (it == 2) {
            if (tid < 64) d_out[((size_t)(b * NCAP + i)) * DCAP + tid] = outv[tid];
        } else {
            const float* Ur = U + tid * PU;
            float dot = 0.f;
#pragma unroll
            for (int d2 = 0; d2 < DCAP; d2++) dot = fmaf(outv[d2], Ur[d2], dot);
            mylog[tid] = dot;
            CLUSTER_SYNC();  // publish logits before next iteration's reads
        }
    }
}

// ---------------- fallback routing (no cluster support): 3 launches ----------------
#define ROUTE_SMEM ((NIN * PU + NIN + 512 + 64 + 8) * 4)

__global__ __launch_bounds__(512) void route_kernel(float* __restrict__ d_out,
                                                    int first, int last, int ping) {
    extern __shared__ float sm[];
    float* U    = sm;
    float* c    = U + NIN * PU;
    float* part = c + NIN;
    float* outv = part + 512;
    float* red  = outv + 64;

    const int i   = blockIdx.x;
    const int b   = blockIdx.y;
    const int tid = threadIdx.x;

    const float4* src4 = (const float4*)(g_uhat + ((size_t)(b * NCAP + i)) * (NIN * DCAP));
#pragma unroll 4
    for (int v = tid; v < NIN * 16; v += 512) {
        float4 t   = src4[v];
        float* dst = U + (v >> 4) * PU + ((v & 15) << 2);
        dst[0] = t.x; dst[1] = t.y; dst[2] = t.z; dst[3] = t.w;
    }

    if (first) {
        c[tid] = 0.0625f;
    } else {
        const float* b_in = ping ? g_b1 : g_b0;
        const float* bp = b_in + ((size_t)b * NCAP) * NIN + tid;
        float vals[NCAP];
        float m = -1e30f;
#pragma unroll
        for (int q = 0; q < NCAP; q++) { vals[q] = bp[q * NIN]; m = fmaxf(m, vals[q]); }
        float s = 0.f;
#pragma unroll
        for (int q = 0; q < NCAP; q++) s += expf(vals[q] - m);
        c[tid] = expf(vals[i] - m) / s;
    }
    __syncthreads();

    {
        const int d = tid & 63, g = tid >> 6;
        float a = 0.f;
#pragma unroll 4
        for (int j = g; j < NIN; j += 8) a = fmaf(c[j], U[j * PU + d], a);
        part[(g << 6) + d] = a;
    }
    __syncthreads();
    if (tid < 64) {
        float s = 0.f;
#pragma unroll
        for (int q = 0; q < 8; q++) s += part[(q << 6) + tid];
        outv[tid] = s;
    }
    __syncthreads();
    if (tid < 64) {
        float o  = outv[tid];
        float sq = o * o;
#pragma unroll
        for (int off = 16; off; off >>= 1) sq += __shfl_xor_sync(0xffffffffu, sq, off);
        if ((tid & 31) == 0) red[tid >> 5] = sq;
    }
    __syncthreads();
    const float inv = 1.0f / sqrtf(red[0] + red[1] + 1e-7f);
    if (tid < 64) outv[tid] *= inv;
    __syncthreads();

    if (last) {
        if (tid < 64) d_out[((size_t)(b * NCAP + i)) * DCAP + tid] = outv[tid];
    } else {
        float* b_out = ping ? g_b0 : g_b1;
        const float* Ur = U + tid * PU;
        float dot = 0.f;
#pragma unroll
        for (int d2 = 0; d2 < DCAP; d2++) dot = fmaf(outv[d2], Ur[d2], dot);
        b_out[((size_t)b * NCAP + i) * NIN + tid] = dot;
    }
}

// ---------------- launch ----------------
extern "C" void kernel_launch(void* const* d_in, const int* in_sizes, int n_in,
                              void* d_out, int out_size) {
    const float* x = (const float*)d_in[0];
    const float* W = (const float*)d_in[1];
    if (in_sizes[0] == DIN * NOUT && in_sizes[1] == (int)((size_t)BATCH * NIN * DIN)) {
        const float* t = x; x = W; W = t;
    }
    float* out = (float*)d_out;

    cudaFuncSetAttribute(gemm_f16, cudaFuncAttributeMaxDynamicSharedMemorySize, GEMM_SMEM);
    cudaFuncSetAttribute(route_fused, cudaFuncAttributeNonPortableClusterSizeAllowed, 1);
    cudaFuncSetAttribute(route_fused, cudaFuncAttributeMaxDynamicSharedMemorySize, RF_SMEM);
    cudaFuncSetAttribute(route_kernel, cudaFuncAttributeMaxDynamicSharedMemorySize, ROUTE_SMEM);

    xh_kernel<<<2048, 256>>>(x);
    wh_kernel<<<dim3(NOUT / 32, DIN / 32), dim3(32, 8)>>>(W);
    gemm_f16<<<dim3(NOUT / GN, (BATCH * NIN) / GM), 512, GEMM_SMEM>>>();

    // fused cluster routing if 16-CTA non-portable clusters are supported
    cudaLaunchConfig_t cfg = {};
    cfg.gridDim  = dim3(NCAP, BATCH, 1);
    cfg.blockDim = dim3(512, 1, 1);
    cfg.dynamicSmemBytes = RF_SMEM;
    cfg.stream = 0;
    cudaLaunchAttribute at[1];
    at[0].id = cudaLaunchAttributeClusterDimension;
    at[0].val.clusterDim.x = NCAP;
    at[0].val.clusterDim.y = 1;
    at[0].val.clusterDim.z = 1;
    cfg.attrs = at;
    cfg.numAttrs = 1;

    int nclus = 0;
    cudaError_t qe = cudaOccupancyMaxActiveClusters(&nclus, route_fused, &cfg);
    if (qe == cudaSuccess && nclus > 0) {
        cudaLaunchKernelEx(&cfg, route_fused, out);
    } else {
        cudaGetLastError();  // clear
        route_kernel<<<dim3(NCAP, BATCH), 512, ROUTE_SMEM>>>(out, 1, 0, 1);
        route_kernel<<<dim3(NCAP, BATCH), 512, ROUTE_SMEM>>>(out, 0, 0, 0);
        route_kernel<<<dim3(NCAP, BATCH), 512, ROUTE_SMEM>>>(out, 0, 1, 1);
    }
}

// round 6
// speedup vs baseline: 2.2230x; 1.3178x over previous
#include <cuda_runtime.h>
#include <cuda_fp16.h>
#include <cstdint>

#define BATCH 64
#define NCAP  16
#define DCAP  64
#define NIN   512
#define DIN   1024
#define NOUT  1024

// ---------------- scratch (allocation-free: __device__ globals) ----------------
__device__ __half g_xh[(size_t)BATCH * NIN * DIN];             // 64 MB, x f16 (rn)
__device__ __half g_wh[(size_t)NOUT * DIN];                    // 2 MB, W^T [n][k] f16 (rn)
__device__ __half g_uh[(size_t)BATCH * NIN * NCAP * DCAP];     // 64 MB, u_hat f16 [b*512+j][cap*64+d]
__device__ float  g_part[16 * BATCH * NCAP * DCAP];            // 4 MB partial sums
__device__ float  g_out[BATCH * NCAP * DCAP];                  // 256 KB current outputs

// ---------------- helpers ----------------
__device__ __forceinline__ uint32_t smem_u32(const void* p) {
    uint32_t a;
    asm("{ .reg .u64 t; cvta.to.shared.u64 t, %1; cvt.u32.u64 %0, t; }" : "=r"(a) : "l"(p));
    return a;
}
__device__ __forceinline__ void cp16(uint32_t dst, const void* src) {
    asm volatile("cp.async.cg.shared.global [%0], [%1], 16;\n" :: "r"(dst), "l"(src));
}
__device__ __forceinline__ void cp_commit() { asm volatile("cp.async.commit_group;\n" ::: "memory"); }

__device__ __forceinline__ void hmma(float* d, const uint32_t* a, const uint32_t* b) {
    asm volatile(
        "mma.sync.aligned.m16n8k16.row.col.f32.f16.f16.f32 "
        "{%0,%1,%2,%3}, {%4,%5,%6,%7}, {%8,%9}, {%0,%1,%2,%3};\n"
        : "+f"(d[0]), "+f"(d[1]), "+f"(d[2]), "+f"(d[3])
        : "r"(a[0]), "r"(a[1]), "r"(a[2]), "r"(a[3]), "r"(b[0]), "r"(b[1]));
}
__device__ __forceinline__ void ldsm_x4(uint32_t* r, uint32_t addr) {
    asm volatile("ldmatrix.sync.aligned.m8n8.x4.shared.b16 {%0,%1,%2,%3}, [%4];"
                 : "=r"(r[0]), "=r"(r[1]), "=r"(r[2]), "=r"(r[3]) : "r"(addr));
}
__device__ __forceinline__ void ldsm_x2(uint32_t* r, uint32_t addr) {
    asm volatile("ldmatrix.sync.aligned.m8n8.x2.shared.b16 {%0,%1}, [%2];"
                 : "=r"(r[0]), "=r"(r[1]) : "r"(addr));
}

// ---------------- prep: x f32 -> f16 rn ----------------
__global__ __launch_bounds__(256) void xh_kernel(const float* __restrict__ X) {
    const size_t n4 = (size_t)BATCH * NIN * DIN / 4;
    for (size_t i = (size_t)blockIdx.x * blockDim.x + threadIdx.x; i < n4;
         i += (size_t)gridDim.x * blockDim.x) {
        float4 v = ((const float4*)X)[i];
        __half2* dst = (__half2*)g_xh + i * 2;
        dst[0] = __floats2half2_rn(v.x, v.y);
        dst[1] = __floats2half2_rn(v.z, v.w);
    }
}

// ---------------- prep: W [k][n] f32 -> W^T [n][k] f16 rn ----------------
__global__ __launch_bounds__(256) void wh_kernel(const float* __restrict__ W) {
    __shared__ float t[32][33];
    const int n0 = blockIdx.x * 32, k0 = blockIdx.y * 32;
    const int tx = threadIdx.x, ty = threadIdx.y;  // 32 x 8
#pragma unroll
    for (int r = 0; r < 32; r += 8)
        t[ty + r][tx] = W[(size_t)(k0 + ty + r) * NOUT + n0 + tx];
    __syncthreads();
#pragma unroll
    for (int r = 0; r < 32; r += 8)
        g_wh[(size_t)(n0 + ty + r) * DIN + k0 + tx] = __float2half_rn(t[tx][ty + r]);
}

// ---------------- GEMM: fp16 mma.sync m16n8k16, CTA 128x256x32, 4-stage, ldmatrix ----------------
#define GM 128
#define GN 256
#define GK 32
#define PIT 80                      // bytes per SMEM row — conflict-free for ldmatrix (all 32 banks)
#define A_SZ (GM * PIT)
#define B_SZ (GN * PIT)
#define ST_SZ (A_SZ + B_SZ)
#define GEMM_SMEM (4 * ST_SZ)       // 122880
#define NKT (DIN / GK)              // 32

__global__ __launch_bounds__(512, 1) void gemm_f16() {
    extern __shared__ char smc[];
    const uint32_t sb = smem_u32(smc);
    const int tid  = threadIdx.x;
    const int lane = tid & 31;
    const int warp = tid >> 5;
    const int wm   = warp >> 3;      // 0..1
    const int wn   = warp & 7;       // 0..7
    const int m0   = blockIdx.y * GM;
    const int n0   = blockIdx.x * GN;

    float acc[4][4][4];
#pragma unroll
    for (int a = 0; a < 4; a++)
#pragma unroll
        for (int b = 0; b < 4; b++)
#pragma unroll
            for (int c = 0; c < 4; c++) acc[a][b][c] = 0.f;

    // ldmatrix per-lane address offsets (within a stage)
    uint32_t a_off[4], b_off[4];
#pragma unroll
    for (int mf = 0; mf < 4; mf++)
        a_off[mf] = (uint32_t)((wm * 64 + mf * 16 + (lane & 7) + ((lane >> 3) & 1) * 8) * PIT
                               + ((lane >> 4) & 1) * 16);
#pragma unroll
    for (int nf = 0; nf < 4; nf++)
        b_off[nf] = (uint32_t)(A_SZ + (wn * 32 + nf * 8 + (lane & 7)) * PIT
                               + ((lane >> 3) & 1) * 16);

    const int ra = tid >> 2, ca = tid & 3;
    auto load_stage = [&](int kt) {
        const uint32_t base = sb + (uint32_t)(kt & 3) * ST_SZ;
        const int kb = kt * GK;
        cp16(base + ra * PIT + ca * 16, g_xh + (size_t)(m0 + ra) * DIN + kb + ca * 8);
        cp16(base + A_SZ + ra * PIT + ca * 16, g_wh + (size_t)(n0 + ra) * DIN + kb + ca * 8);
        cp16(base + A_SZ + (128 + ra) * PIT + ca * 16,
             g_wh + (size_t)(n0 + 128 + ra) * DIN + kb + ca * 8);
        cp_commit();
    };

    load_stage(0);
    load_stage(1);
    load_stage(2);

    for (int kt = 0; kt < NKT; kt++) {
        if (kt < NKT - 2)       asm volatile("cp.async.wait_group 2;\n" ::: "memory");
        else if (kt == NKT - 2) asm volatile("cp.async.wait_group 1;\n" ::: "memory");
        else                    asm volatile("cp.async.wait_group 0;\n" ::: "memory");
        __syncthreads();

        const uint32_t stg = sb + (uint32_t)(kt & 3) * ST_SZ;
#pragma unroll
        for (int ks = 0; ks < 2; ks++) {
            const int kkb = ks * 32;
            uint32_t af[4][4], bf[4][2];
#pragma unroll
            for (int mf = 0; mf < 4; mf++) ldsm_x4(af[mf], stg + a_off[mf] + kkb);
#pragma unroll
            for (int nf = 0; nf < 4; nf++) ldsm_x2(bf[nf], stg + b_off[nf] + kkb);
#pragma unroll
            for (int mf = 0; mf < 4; mf++)
#pragma unroll
                for (int nf = 0; nf < 4; nf++) hmma(acc[mf][nf], af[mf], bf[nf]);
        }

        if (kt + 3 < NKT) load_stage(kt + 3);
    }

    // epilogue: u_hat f16, natural row-major [row = b*512+j][col = cap*64+d]
#pragma unroll
    for (int mf = 0; mf < 4; mf++) {
#pragma unroll
        for (int nf = 0; nf < 4; nf++) {
            const int row = m0 + wm * 64 + mf * 16 + (lane >> 2);
            const int col = n0 + wn * 32 + nf * 8 + ((lane & 3) << 1);
            __half2* d0 = (__half2*)(g_uh + (size_t)row * NOUT + col);
            __half2* d1 = (__half2*)(g_uh + (size_t)(row + 8) * NOUT + col);
            *d0 = __floats2half2_rn(acc[mf][nf][0], acc[mf][nf][1]);
            *d1 = __floats2half2_rn(acc[mf][nf][2], acc[mf][nf][3]);
        }
    }
}

// ---------------- routing pass: one streaming pass over u_hat per iteration ----------------
// CTA = (j-chunk of 32, batch). 512 threads, ~71 KB SMEM, 2 CTAs/SM.
#define TJ 32
#define UPITCH_B 2064                    // bytes per u row in SMEM (1032 halves; 516 words, %32==4)
#define UPITCH_W 516
#define OUT_PIT 66                        // floats, out_s pitch
#define SM_U    0
#define SM_OUT  (TJ * UPITCH_B)           // 66048
#define SM_C    (SM_OUT + 16 * OUT_PIT * 4)
#define PASS_SMEM (SM_C + 32 * 17 * 4 + 16)

__global__ __launch_bounds__(512, 2) void route_pass(int it) {
    extern __shared__ char smc[];
    const uint32_t sb = smem_u32(smc);
    uint32_t* u_w  = (uint32_t*)smc;                 // u as packed half2 words
    float*    outs = (float*)(smc + SM_OUT);         // [16][66]
    float*    c_s  = (float*)(smc + SM_C);           // [32][17]

    const int chunk = blockIdx.x;   // 0..15
    const int b     = blockIdx.y;   // 0..63
    const int tid   = threadIdx.x;

    // stage u[b, chunk*32 .. +31, :, :]  (32 rows x 2KB) via cp.async
    const __half* src = g_uh + ((size_t)(b * NIN + chunk * TJ)) * NOUT;
#pragma unroll
    for (int c = tid; c < TJ * 128; c += 512) {
        const int jl = c >> 7, c16 = c & 127;
        cp16(sb + SM_U + jl * UPITCH_B + c16 * 16, src + (size_t)jl * NOUT + c16 * 8);
    }
    cp_commit();

    if (it > 0) {
        // stage out_prev[b] (1024 floats) into [i][d] with pitch 66
        for (int e = tid; e < 1024; e += 512)
            outs[(e >> 6) * OUT_PIT + (e & 63)] = g_out[b * 1024 + e];
    }
    asm volatile("cp.async.wait_group 0;\n" ::: "memory");
    __syncthreads();

    if (it > 0) {
        // logits: thread (jl = tid>>4, i = tid&15): dot(out_prev[i], u[jl][i][:])
        const int jl = tid >> 4, i = tid & 15;
        const uint32_t* up = u_w + jl * UPITCH_W + i * 32;
        const float*    op = outs + i * OUT_PIT;
        float dot = 0.f;
#pragma unroll
        for (int t = 0; t < 32; t++) {
            const int p = (2 * i + t) & 31;               // staggered: avoids 16-way conflicts
            const __half2 h = *(const __half2*)(up + p);
            const float2  f = __half22float2(h);
            dot = fmaf(f.x, op[2 * p], fmaf(f.y, op[2 * p + 1], dot));
        }
        // softmax over the 16 capsules (16-lane shuffle groups)
        float m = dot;
#pragma unroll
        for (int off = 8; off; off >>= 1) m = fmaxf(m, __shfl_xor_sync(0xffffffffu, m, off));
        const float e = expf(dot - m);
        float s = e;
#pragma unroll
        for (int off = 8; off; off >>= 1) s += __shfl_xor_sync(0xffffffffu, s, off);
        c_s[jl * 17 + i] = e / s;
        __syncthreads();
    }

    // accumulate: thread (i = tid>>5, dp = tid&31): sum_j c[j][i] * u[j][i][2dp..2dp+1]
    const int i2 = tid >> 5, dp = tid & 31;
    float ax = 0.f, ay = 0.f;
    const uint32_t* ub = u_w + i2 * 32 + dp;
#pragma unroll
    for (int jl = 0; jl < TJ; jl++) {
        const float cv = (it == 0) ? 0.0625f : c_s[jl * 17 + i2];
        const float2 f = __half22float2(*(const __half2*)(ub + jl * UPITCH_W));
        ax = fmaf(cv, f.x, ax);
        ay = fmaf(cv, f.y, ay);
    }
    float2 r;
    r.x = ax; r.y = ay;
    *(float2*)&g_part[((size_t)(chunk * BATCH + b)) * 1024 + i2 * 64 + dp * 2] = r;
}

// ---------------- reduce partials + squash ----------------
__global__ __launch_bounds__(512) void reduce_squash(float* __restrict__ d_out, int last) {
    const int b = blockIdx.x, tid = threadIdx.x;
    const int e0 = tid * 2;
    float vx = 0.f, vy = 0.f;
#pragma unroll
    for (int ch = 0; ch < 16; ch++) {
        const float2 p = *(const float2*)&g_part[((size_t)(ch * BATCH + b)) * 1024 + e0];
        vx += p.x; vy += p.y;
    }
    // squash per capsule: warp == one capsule (tid>>5 == e0>>6)
    float sq = vx * vx + vy * vy;
#pragma unroll
    for (int off = 16; off; off >>= 1) sq += __shfl_xor_sync(0xffffffffu, sq, off);
    const float inv = 1.0f / sqrtf(sq + 1e-7f);
    float2 r;
    r.x = vx * inv; r.y = vy * inv;
    if (last) *(float2*)&d_out[b * 1024 + e0] = r;
    else      *(float2*)&g_out[b * 1024 + e0] = r;
}

// ---------------- launch ----------------
extern "C" void kernel_launch(void* const* d_in, const int* in_sizes, int n_in,
                              void* d_out, int out_size) {
    const float* x = (const float*)d_in[0];
    const float* W = (const float*)d_in[1];
    if (in_sizes[0] == DIN * NOUT && in_sizes[1] == (int)((size_t)BATCH * NIN * DIN)) {
        const float* t = x; x = W; W = t;
    }
    float* out = (float*)d_out;

    cudaFuncSetAttribute(gemm_f16, cudaFuncAttributeMaxDynamicSharedMemorySize, GEMM_SMEM);
    cudaFuncSetAttribute(route_pass, cudaFuncAttributeMaxDynamicSharedMemorySize, PASS_SMEM);

    xh_kernel<<<2048, 256>>>(x);
    wh_kernel<<<dim3(NOUT / 32, DIN / 32), dim3(32, 8)>>>(W);
    gemm_f16<<<dim3(NOUT / GN, (BATCH * NIN) / GM), 512, GEMM_SMEM>>>();

    route_pass<<<dim3(16, BATCH), 512, PASS_SMEM>>>(0);
    reduce_squash<<<BATCH, 512>>>(out, 0);
    route_pass<<<dim3(16, BATCH), 512, PASS_SMEM>>>(1);
    reduce_squash<<<BATCH, 512>>>(out, 0);
    route_pass<<<dim3(16, BATCH), 512, PASS_SMEM>>>(2);
    reduce_squash<<<BATCH, 512>>>(out, 1);
}